// round 5
// baseline (speedup 1.0000x reference)
#include <cuda_runtime.h>

typedef unsigned long long u64;
typedef unsigned int u32;

#define NROWS  65536
#define KC     4096
#define DIM    64
#define ROWS_B 128
#define NBLK   512
#define CTA    256
#define NTILES 64
#define MARGINI 214748      // 4e-4 * 2^29

// static smem layout (bytes), total 32768
#define SH_A    0           // Z8 plane: 128 rows * 80B
#define SH_B    10240       // + buf*10240 + plane*5120 (wh, wl tiles, 64 rows * 80B)
#define SH_W2Q  30720       // 2 bufs * 64 ints
#define SH_BIDX 31232       // 128 ints
#define SH_RED  31744       // 256 floats

__device__ signed char g_wh8[KC * DIM];
__device__ signed char g_wl8[KC * DIM];
__device__ float g_w2[KC];
__device__ int   g_w2q[KC];
__device__ float g_part[NBLK];
__device__ int   g_cnt;

// ---------------------------------------------------------------------------
__device__ __forceinline__ u32 smem_u32(const void* p) {
    u32 a;
    asm("{ .reg .u64 t; cvta.to.shared.u64 t, %1; cvt.u32.u64 %0, t; }"
        : "=r"(a) : "l"(p));
    return a;
}
__device__ __forceinline__ void cp16(u32 dst, const void* src) {
    asm volatile("cp.async.cg.shared.global [%0], [%1], 16;" :: "r"(dst), "l"(src));
}
#define CP_COMMIT() asm volatile("cp.async.commit_group;" ::: "memory")
#define CP_WAIT0()  asm volatile("cp.async.wait_group 0;" ::: "memory")

__device__ __forceinline__ void ldsm4(u32& r0, u32& r1, u32& r2, u32& r3, u32 a) {
    asm volatile("ldmatrix.sync.aligned.m8n8.x4.shared.b16 {%0,%1,%2,%3}, [%4];"
                 : "=r"(r0), "=r"(r1), "=r"(r2), "=r"(r3) : "r"(a));
}
// s8 IMMA: d = a*b + c ; MMA_IZ starts with c = 0
#define MMA_IZ(d, a, b0, b1)                                                  \
    asm volatile("mma.sync.aligned.m16n8k32.row.col.s32.s8.s8.s32 "           \
        "{%0,%1,%2,%3},{%4,%5,%6,%7},{%8,%9},{%10,%10,%10,%10};"              \
        : "=r"((d)[0]), "=r"((d)[1]), "=r"((d)[2]), "=r"((d)[3])              \
        : "r"((a)[0]), "r"((a)[1]), "r"((a)[2]), "r"((a)[3]),                 \
          "r"(b0), "r"(b1), "r"(0))
#define MMA_I(d, a, b0, b1)                                                   \
    asm volatile("mma.sync.aligned.m16n8k32.row.col.s32.s8.s8.s32 "           \
        "{%0,%1,%2,%3},{%4,%5,%6,%7},{%8,%9},{%0,%1,%2,%3};"                  \
        : "+r"((d)[0]), "+r"((d)[1]), "+r"((d)[2]), "+r"((d)[3])              \
        : "r"((a)[0]), "r"((a)[1]), "r"((a)[2]), "r"((a)[3]), "r"(b0), "r"(b1))

#define TRACK(p, Dv, kv) do {                                                 \
    int _D = (Dv);                                                            \
    if (_D < s4[p]) {                                                         \
        if (_D < s2[p]) {                                                     \
            if (_D < s1[p]) { s4[p]=s3[p]; s3[p]=s2[p]; k3[p]=k2[p];          \
                              s2[p]=s1[p]; k2[p]=k1[p]; s1[p]=_D; k1[p]=(kv);}\
            else { s4[p]=s3[p]; s3[p]=s2[p]; k3[p]=k2[p]; s2[p]=_D; k2[p]=(kv);}\
        } else {                                                              \
            if (_D < s3[p]) { s4[p]=s3[p]; s3[p]=_D; k3[p]=(kv); }            \
            else s4[p] = _D;                                                  \
        }                                                                     \
    } } while (0)

// ---------------------------------------------------------------------------
// prep: exact w2 (sequential ascending, R1/R2/R4-proven order) + int split of -2W
// ---------------------------------------------------------------------------
__global__ void prep_kernel(const float* __restrict__ W) {
    int k = blockIdx.x * 256 + threadIdx.x;      // grid 16 x 256
    const float* w = W + (size_t)k * DIM;
    float s = 0.0f;
    #pragma unroll
    for (int jw = 0; jw < 16; jw++) {
        u32 h = 0, l = 0;
        #pragma unroll
        for (int b = 0; b < 4; b++) {
            float wv = w[jw * 4 + b];
            s = __fmaf_rn(wv, wv, s);
            int W16 = __float2int_rn(wv * -67108864.0f);   // -2w * 2^25 (exact fold)
            int wh = (W16 + 128) >> 8;
            int wl = W16 - (wh << 8);                      // in [-128,127]
            h |= ((u32)wh & 0xffu) << (8 * b);
            l |= ((u32)wl & 0xffu) << (8 * b);
        }
        ((u32*)g_wh8)[k * 16 + jw] = h;
        ((u32*)g_wl8)[k * 16 + jw] = l;
    }
    g_w2[k] = s;
    g_w2q[k] = __float2int_rn(s * 536870912.0f);           // w2 * 2^29
}

// ---------------------------------------------------------------------------
__device__ __forceinline__ u64 rescore_g(int k, const float* __restrict__ zr,
                                         const float* __restrict__ W) {
    const float* wr = W + (size_t)k * DIM;
    float z2 = 0.0f, s = 0.0f;
    #pragma unroll 16
    for (int j = 0; j < DIM; j++) {
        float zj = zr[j];
        z2 = __fmaf_rn(zj, zj, z2);
        s  = __fmaf_rn(zj, wr[j], s);
    }
    float D = __fsub_rn(__fadd_rn(z2, g_w2[k]), __fmul_rn(2.0f, s));
    return ((u64)__float_as_uint(D) << 32) | (u32)k;
}

__device__ __forceinline__ void load_tile(u32 sb, int t, int buf, int tid) {
    int code = tid >> 2, ch = tid & 3;
    size_t gsrc = ((size_t)t * 64 + code) * 64 + ch * 16;
    u32 dstb = sb + SH_B + buf * 10240 + code * 80 + ch * 16;
    cp16(dstb,        (const char*)g_wh8 + gsrc);
    cp16(dstb + 5120, (const char*)g_wl8 + gsrc);
    if (tid < 16)
        cp16(sb + SH_W2Q + buf * 256 + tid * 16,
             (const char*)g_w2q + (size_t)t * 256 + tid * 16);
}

// ---------------------------------------------------------------------------
__global__ __launch_bounds__(CTA, 2)
void vq_main(const float* __restrict__ z, const float* __restrict__ W,
             float* __restrict__ out, int off) {
    __shared__ __align__(16) char sm[32768];
    const u32 sb = smem_u32(sm);
    const int tid = threadIdx.x, wid = tid >> 5, lane = tid & 31;
    const int tg = lane & 3, rq = lane >> 2;
    int* bidx = (int*)(sm + SH_BIDX);

    load_tile(sb, 0, 0, tid);
    CP_COMMIT();

    // ---- build Z8 plane: Z8 = rint(16*z), clipped to +-127 ----
    const float4* gz = (const float4*)(z + (size_t)blockIdx.x * ROWS_B * DIM);
    #pragma unroll
    for (int q = 0; q < 8; q++) {
        int i = tid + CTA * q;              // 2048 float4
        int r = i >> 4, c4 = i & 15;
        float4 v = gz[i];
        int b0 = __float2int_rn(fminf(fmaxf(v.x * 16.0f, -127.0f), 127.0f));
        int b1 = __float2int_rn(fminf(fmaxf(v.y * 16.0f, -127.0f), 127.0f));
        int b2 = __float2int_rn(fminf(fmaxf(v.z * 16.0f, -127.0f), 127.0f));
        int b3 = __float2int_rn(fminf(fmaxf(v.w * 16.0f, -127.0f), 127.0f));
        u32 pk = ((u32)b0 & 0xffu) | (((u32)b1 & 0xffu) << 8)
               | (((u32)b2 & 0xffu) << 16) | (((u32)b3 & 0xffu) << 24);
        *(u32*)(sm + SH_A + r * 80 + c4 * 4) = pk;
    }
    CP_WAIT0();
    __syncthreads();

    // ---- A fragments (m16k32 x 2 chunks, held all tiles) ----
    u32 az0[4], az1[4];
    {
        int mat = lane >> 3, rl = lane & 7;
        u32 ab = sb + SH_A + (u32)((wid * 16 + (mat & 1) * 8 + rl) * 80
                                   + (mat >> 1) * 16);
        ldsm4(az0[0], az0[1], az0[2], az0[3], ab);
        ldsm4(az1[0], az1[1], az1[2], az1[3], ab + 32);
    }

    int s1[2], s2[2], s3[2], s4[2], k1[2], k2[2], k3[2];
    #pragma unroll
    for (int p = 0; p < 2; p++) {
        s1[p] = s2[p] = s3[p] = s4[p] = 0x7fffffff;
        k1[p] = k2[p] = k3[p] = 0;
    }

    const u32 blane = (u32)((lane & 7) * 80 + (lane >> 3) * 16);

    for (int t = 0; t < NTILES; t++) {
        int buf = t & 1;
        if (t + 1 < NTILES) { load_tile(sb, t + 1, buf ^ 1, tid); CP_COMMIT(); }

        const u32 bhB = sb + SH_B + buf * 10240;
        const u32 blB = bhB + 5120;
        const int* w2qb = (const int*)(sm + SH_W2Q + buf * 256);

        #pragma unroll
        for (int g = 0; g < 8; g++) {
            u32 bh[4], bl[4];
            ldsm4(bh[0], bh[1], bh[2], bh[3], bhB + blane + g * 640);
            ldsm4(bl[0], bl[1], bl[2], bl[3], blB + blane + g * 640);
            int a1[4], a2[4];
            MMA_IZ(a1, az0, bh[0], bh[1]);
            MMA_IZ(a2, az0, bl[0], bl[1]);
            MMA_I (a1, az1, bh[2], bh[3]);
            MMA_I (a2, az1, bl[2], bl[3]);

            int2 wq = *(const int2*)(w2qb + g * 8 + 2 * tg);
            int kb = t * 64 + g * 8 + 2 * tg;
            TRACK(0, ((a1[0] << 8) + a2[0]) + wq.x, kb);
            TRACK(0, ((a1[1] << 8) + a2[1]) + wq.y, kb + 1);
            TRACK(1, ((a1[2] << 8) + a2[2]) + wq.x, kb);
            TRACK(1, ((a1[3] << 8) + a2[3]) + wq.y, kb + 1);
        }
        if (t + 1 < NTILES) { CP_WAIT0(); __syncthreads(); }
    }

    // ---- per-row candidate combine + exact rescore ----
    const float* zbase = z + (size_t)blockIdx.x * ROWS_B * DIM;
    int flag[2];
    #pragma unroll
    for (int p = 0; p < 2; p++) {
        int rowc = wid * 16 + p * 8 + rq;
        int gm = s1[p];
        gm = min(gm, __shfl_xor_sync(0xffffffffu, gm, 1));
        gm = min(gm, __shfl_xor_sync(0xffffffffu, gm, 2));
        int thr = gm + MARGINI;
        flag[p] = (s4[p] <= thr) ? 1 : 0;

        const float* zr = zbase + rowc * DIM;
        u64 key = ~0ull;
        if (s1[p] <= thr) { u64 v = rescore_g(k1[p], zr, W); if (v < key) key = v; }
        if (s2[p] <= thr) { u64 v = rescore_g(k2[p], zr, W); if (v < key) key = v; }
        if (s3[p] <= thr) { u64 v = rescore_g(k3[p], zr, W); if (v < key) key = v; }
        u64 o = __shfl_xor_sync(0xffffffffu, key, 1); if (o < key) key = o;
        o = __shfl_xor_sync(0xffffffffu, key, 2); if (o < key) key = o;
        if (tg == 0) bidx[rowc] = (int)(key & 0xffffffffULL);
    }

    // ---- cooperative exact full-rescan for flagged rows (rare) ----
    __syncwarp();
    #pragma unroll
    for (int p = 0; p < 2; p++) {
        unsigned f = __ballot_sync(0xffffffffu, flag[p] != 0);
        for (int r = 0; r < 8; r++) {
            if ((f >> (4 * r)) & 0xF) {
                int rowc = wid * 16 + p * 8 + r;
                const float* zr = zbase + rowc * DIM;
                u64 bk = ~0ull;
                for (int k = lane; k < KC; k += 32) {
                    u64 v = rescore_g(k, zr, W);
                    if (v < bk) bk = v;
                }
                #pragma unroll
                for (int o2 = 16; o2; o2 >>= 1) {
                    u64 v = __shfl_xor_sync(0xffffffffu, bk, o2);
                    if (v < bk) bk = v;
                }
                if (lane == 0) bidx[rowc] = (int)(bk & 0xffffffffULL);
            }
        }
    }
    __syncthreads();

    // ---- fused epilogue: gather + STE + loss partial ----
    float lsum = 0.0f;
    const size_t obase = (size_t)blockIdx.x * ROWS_B * DIM + off;
    #pragma unroll
    for (int q = 0; q < 8; q++) {
        int i = tid + CTA * q;
        int row = i >> 4, c4 = i & 15;
        float4 zv = gz[i];
        const float* wr = W + (size_t)bidx[row] * DIM + c4 * 4;
        float4 wv = *(const float4*)wr;
        float zz[4] = {zv.x, zv.y, zv.z, zv.w};
        float ww[4] = {wv.x, wv.y, wv.z, wv.w};
        #pragma unroll
        for (int c = 0; c < 4; c++) {
            float d = __fsub_rn(zz[c], ww[c]);
            lsum = __fmaf_rn(d, d, lsum);
            out[obase + i * 4 + c] = __fadd_rn(zz[c], __fsub_rn(ww[c], zz[c]));
        }
    }

    float* red = (float*)(sm + SH_RED);
    red[tid] = lsum;
    __syncthreads();
    for (int s = CTA / 2; s > 0; s >>= 1) {
        if (tid < s) red[tid] = __fadd_rn(red[tid], red[tid + s]);
        __syncthreads();
    }
    __shared__ int lastf;
    if (tid == 0) {
        g_part[blockIdx.x] = red[0];
        __threadfence();
        lastf = (atomicAdd(&g_cnt, 1) == NBLK - 1) ? 1 : 0;
    }
    __syncthreads();

    // ---- last CTA: deterministic final loss reduction ----
    if (lastf) {
        __threadfence();
        float s = __fadd_rn(g_part[tid], g_part[tid + 256]);
        red[tid] = s;
        __syncthreads();
        for (int st = CTA / 2; st > 0; st >>= 1) {
            if (tid < st) red[tid] = __fadd_rn(red[tid], red[tid + st]);
            __syncthreads();
        }
        if (tid == 0) {
            if (off) out[0] = __fmul_rn(0.25f, __fdiv_rn(red[0], 4194304.0f));
            g_cnt = 0;   // reset for next graph replay
        }
    }
}

// ---------------------------------------------------------------------------
extern "C" void kernel_launch(void* const* d_in, const int* in_sizes, int n_in,
                              void* d_out, int out_size) {
    const float* z = (const float*)d_in[0];
    const float* W = (const float*)d_in[1];
    if (n_in >= 2 && in_sizes[0] < in_sizes[1]) {
        const float* t = z; z = W; W = t;
    }
    float* out = (float*)d_out;
    const int off = (out_size > NROWS * DIM) ? 1 : 0;

    prep_kernel<<<16, 256>>>(W);
    vq_main<<<NBLK, CTA>>>(z, W, out, off);
}

// round 6
// speedup vs baseline: 2.0530x; 2.0530x over previous
#include <cuda_runtime.h>
#include <cuda_bf16.h>

typedef unsigned long long u64;
typedef unsigned int u32;

#define NROWS  65536
#define KC     4096
#define DIM    64
#define ROWS_B 128
#define NBLK   512
#define CTA    256
#define NTILES 64
#define MARGIN 2e-4f
#define ZP     68

// dynamic smem layout (bytes)
#define OFF_Z    0          // 128*68*4 = 34816
#define OFF_Z2   34816      // 512
#define OFF_A    35328      // 16384 (bf16 z plane, 128 rows * 128B, SW128)
#define OFF_B(b) (51712 + (b)*8192)   // 64 codes * 128B per buf
#define OFF_W2(b) (68096 + (b)*256)
#define OFF_BIDX 68608
#define OFF_RED  69120
#define SMEM_BYTES 70144

#define SWZ(x) ((x) ^ (((x) >> 3) & 0x70))

__device__ __nv_bfloat16 g_whi[KC * DIM];
__device__ float g_w2[KC];
__device__ float g_part[NBLK];
__device__ int   g_cnt;

// ---------------------------------------------------------------------------
__device__ __forceinline__ u32 smem_u32(const void* p) {
    u32 a;
    asm("{ .reg .u64 t; cvta.to.shared.u64 t, %1; cvt.u32.u64 %0, t; }"
        : "=r"(a) : "l"(p));
    return a;
}
__device__ __forceinline__ void cp16(u32 dst, const void* src) {
    asm volatile("cp.async.cg.shared.global [%0], [%1], 16;" :: "r"(dst), "l"(src));
}
#define CP_COMMIT() asm volatile("cp.async.commit_group;" ::: "memory")
#define CP_WAIT0()  asm volatile("cp.async.wait_group 0;" ::: "memory")

__device__ __forceinline__ void ldsm4(u32& r0, u32& r1, u32& r2, u32& r3, u32 a) {
    asm volatile("ldmatrix.sync.aligned.m8n8.x4.shared.b16 {%0,%1,%2,%3}, [%4];"
                 : "=r"(r0), "=r"(r1), "=r"(r2), "=r"(r3) : "r"(a));
}
#define MMA(d, a, b0, b1)                                                     \
    asm volatile("mma.sync.aligned.m16n8k16.row.col.f32.bf16.bf16.f32 "       \
        "{%0,%1,%2,%3},{%4,%5,%6,%7},{%8,%9},{%0,%1,%2,%3};"                  \
        : "+f"((d)[0]), "+f"((d)[1]), "+f"((d)[2]), "+f"((d)[3])              \
        : "r"((a)[0]), "r"((a)[1]), "r"((a)[2]), "r"((a)[3]), "r"(b0), "r"(b1))

// top-3 (with indices) + s4 overflow sentinel
#define TRACK(p, Dv, kv) do {                                                 \
    float _D = (Dv);                                                          \
    if (_D < s4[p]) {                                                         \
        if (_D < s2[p]) {                                                     \
            if (_D < s1[p]) { s4[p]=s3[p]; s3[p]=s2[p]; k3[p]=k2[p];          \
                              s2[p]=s1[p]; k2[p]=k1[p]; s1[p]=_D; k1[p]=(kv);}\
            else { s4[p]=s3[p]; s3[p]=s2[p]; k3[p]=k2[p]; s2[p]=_D; k2[p]=(kv);}\
        } else {                                                              \
            if (_D < s3[p]) { s4[p]=s3[p]; s3[p]=_D; k3[p]=(kv); }            \
            else s4[p] = _D;                                                  \
        }                                                                     \
    } } while (0)

// ---------------------------------------------------------------------------
// prep: exact w2 (sequential ascending, proven order) + bf16(-2w)
// ---------------------------------------------------------------------------
__global__ void prep_kernel(const float* __restrict__ W) {
    int k = blockIdx.x * 256 + threadIdx.x;      // grid 16 x 256
    const float* w = W + (size_t)k * DIM;
    float s = 0.0f;
    #pragma unroll 16
    for (int j = 0; j < DIM; j++) {
        float wv = w[j];
        s = __fmaf_rn(wv, wv, s);
        g_whi[k * DIM + j] = __float2bfloat16(-2.0f * wv);
    }
    g_w2[k] = s;
}

// ---------------------------------------------------------------------------
__device__ __forceinline__ u64 rescore(int k, const float* zr, float z2r,
                                       const float* __restrict__ W) {
    const float* wr = W + (size_t)k * DIM;
    float s = 0.0f;
    #pragma unroll 8
    for (int j = 0; j < DIM; j++) s = __fmaf_rn(zr[j], wr[j], s);
    float D = __fsub_rn(__fadd_rn(z2r, g_w2[k]), __fmul_rn(2.0f, s));
    return ((u64)__float_as_uint(D) << 32) | (u32)k;
}

__device__ __forceinline__ void load_tile(u32 sb, int t, int buf, int tid) {
    const char* bh = (const char*)g_whi;
    size_t gbase = (size_t)t * 64 * 128;         // 64 codes * 128B
    #pragma unroll
    for (int q = 0; q < 2; q++) {
        int i = tid + CTA * q;                   // 512 chunks of 16B
        cp16(sb + OFF_B(buf) + SWZ((u32)(i * 16)), bh + gbase + (size_t)i * 16);
    }
    if (tid < 16)
        cp16(sb + OFF_W2(buf) + tid * 16,
             (const char*)g_w2 + (size_t)t * 256 + tid * 16);
}

// ---------------------------------------------------------------------------
__global__ __launch_bounds__(CTA, 2)
void vq_main(const float* __restrict__ z, const float* __restrict__ W,
             float* __restrict__ out, int off) {
    extern __shared__ char sm[];
    const u32 sb = smem_u32(sm);
    const int tid = threadIdx.x, wid = tid >> 5, lane = tid & 31;
    const int tg = lane & 3, rq = lane >> 2;
    float* zsm = (float*)(sm + OFF_Z);
    float* z2s = (float*)(sm + OFF_Z2);
    int* bidx = (int*)(sm + OFF_BIDX);

    load_tile(sb, 0, 0, tid);
    CP_COMMIT();

    // ---- z -> smem (coalesced) ----
    const float4* gz = (const float4*)(z + (size_t)blockIdx.x * ROWS_B * DIM);
    #pragma unroll
    for (int q = 0; q < 8; q++) {
        int i = tid + CTA * q;                   // 2048 float4
        int r = i >> 4, c = i & 15;
        *(float4*)(zsm + r * ZP + c * 4) = gz[i];
    }
    __syncthreads();

    // ---- build A = bf16(z) (SW128) + z2 (sequential, proven) ----
    #pragma unroll
    for (int q = 0; q < 16; q++) {
        int i = tid + CTA * q;                   // 4096 u32 slots
        int r = i >> 5, pr = i & 31;
        float a = zsm[r * ZP + 2 * pr], b = zsm[r * ZP + 2 * pr + 1];
        __nv_bfloat162 h2 = __halves2bfloat162(__float2bfloat16(a),
                                               __float2bfloat16(b));
        *(u32*)(sm + OFF_A + SWZ((u32)(r * 128 + pr * 4))) = *(u32*)&h2;
    }
    if (tid < ROWS_B) {
        float s = 0.0f;
        #pragma unroll 8
        for (int j = 0; j < DIM; j++) {
            float v = zsm[tid * ZP + j];
            s = __fmaf_rn(v, v, s);
        }
        z2s[tid] = s;
    }
    CP_WAIT0();
    __syncthreads();

    // ---- A fragments (held all tiles) ----
    u32 ahi[4][4];
    {
        int mat = lane >> 3, rl = lane & 7;
        u32 abase = (u32)((wid * 16 + (mat & 1) * 8 + rl) * 128 + (mat >> 1) * 16);
        #pragma unroll
        for (int kc = 0; kc < 4; kc++) {
            u32 sw = SWZ(abase + kc * 32);
            ldsm4(ahi[kc][0], ahi[kc][1], ahi[kc][2], ahi[kc][3], sb + OFF_A + sw);
        }
    }

    float s1[2], s2[2], s3[2], s4[2];
    int k1[2], k2[2], k3[2];
    #pragma unroll
    for (int p = 0; p < 2; p++) {
        s1[p] = s2[p] = s3[p] = s4[p] = __int_as_float(0x7f800000);
        k1[p] = k2[p] = k3[p] = 0;
    }

    const int brl = lane & 7;
    const u32 bkoff = (u32)(((lane >> 4) * 32) + (((lane >> 3) & 1) * 16));

    for (int t = 0; t < NTILES; t++) {
        int buf = t & 1;
        if (t + 1 < NTILES) { load_tile(sb, t + 1, buf ^ 1, tid); CP_COMMIT(); }

        const u32 bhB = sb + OFF_B(buf);
        const float* w2b = (const float*)(sm + OFF_W2(buf));

        float d[8][4];
        #pragma unroll
        for (int n = 0; n < 8; n++)
            #pragma unroll
            for (int c = 0; c < 4; c++) d[n][c] = 0.0f;

        #pragma unroll
        for (int g = 0; g < 2; g++) {
            #pragma unroll
            for (int kp = 0; kp < 2; kp++) {
                u32 bh[4][4];
                #pragma unroll
                for (int i = 0; i < 4; i++) {
                    u32 o = SWZ((u32)(((g * 4 + i) * 8 + brl) * 128)
                                + (u32)(2 * kp * 32) + bkoff);
                    ldsm4(bh[i][0], bh[i][1], bh[i][2], bh[i][3], bhB + o);
                }
                // round-robin over 4 independent accumulators
                #pragma unroll
                for (int i = 0; i < 4; i++) MMA(d[g*4+i], ahi[2*kp],   bh[i][0], bh[i][1]);
                #pragma unroll
                for (int i = 0; i < 4; i++) MMA(d[g*4+i], ahi[2*kp+1], bh[i][2], bh[i][3]);
            }
        }

        // ---- extract + top-3 tracking ----
        #pragma unroll
        for (int nc = 0; nc < 8; nc++) {
            float2 wv = *(const float2*)(w2b + nc * 8 + 2 * tg);
            int kb = t * 64 + nc * 8 + 2 * tg;
            TRACK(0, __fadd_rn(wv.x, d[nc][0]), kb);
            TRACK(0, __fadd_rn(wv.y, d[nc][1]), kb + 1);
            TRACK(1, __fadd_rn(wv.x, d[nc][2]), kb);
            TRACK(1, __fadd_rn(wv.y, d[nc][3]), kb + 1);
        }
        if (t + 1 < NTILES) { CP_WAIT0(); __syncthreads(); }
    }

    // ---- per-row combine + exact rescore (hard-margin candidates) ----
    int flag[2];
    #pragma unroll
    for (int p = 0; p < 2; p++) {
        int rowc = wid * 16 + p * 8 + rq;
        float gm = s1[p];
        gm = fminf(gm, __shfl_xor_sync(0xffffffffu, gm, 1));
        gm = fminf(gm, __shfl_xor_sync(0xffffffffu, gm, 2));
        float thr = __fadd_rn(gm, MARGIN);
        flag[p] = (s4[p] <= thr) ? 1 : 0;

        const float* zr = zsm + rowc * ZP;
        float z2r = z2s[rowc];
        u64 key = ~0ull;
        if (s1[p] <= thr) { u64 v = rescore(k1[p], zr, z2r, W); if (v < key) key = v; }
        if (s2[p] <= thr) { u64 v = rescore(k2[p], zr, z2r, W); if (v < key) key = v; }
        if (s3[p] <= thr) { u64 v = rescore(k3[p], zr, z2r, W); if (v < key) key = v; }
        u64 o = __shfl_xor_sync(0xffffffffu, key, 1); if (o < key) key = o;
        o = __shfl_xor_sync(0xffffffffu, key, 2); if (o < key) key = o;
        if (tg == 0) bidx[rowc] = (int)(key & 0xffffffffULL);
    }

    // ---- cooperative exact full-rescan for overflowed rows (rare) ----
    __syncwarp();
    #pragma unroll
    for (int p = 0; p < 2; p++) {
        unsigned f = __ballot_sync(0xffffffffu, flag[p] != 0);
        for (int r = 0; r < 8; r++) {
            if ((f >> (4 * r)) & 0xF) {
                int rowc = wid * 16 + p * 8 + r;
                const float* zr = zsm + rowc * ZP;
                float z2r = z2s[rowc];
                u64 bk = ~0ull;
                for (int k = lane; k < KC; k += 32) {
                    u64 v = rescore(k, zr, z2r, W);
                    if (v < bk) bk = v;
                }
                #pragma unroll
                for (int o2 = 16; o2; o2 >>= 1) {
                    u64 v = __shfl_xor_sync(0xffffffffu, bk, o2);
                    if (v < bk) bk = v;
                }
                if (lane == 0) bidx[rowc] = (int)(bk & 0xffffffffULL);
            }
        }
    }
    __syncthreads();

    // ---- fused epilogue: gather + STE + loss partial ----
    float lsum = 0.0f;
    const size_t obase = (size_t)blockIdx.x * ROWS_B * DIM + off;
    #pragma unroll
    for (int q = 0; q < 8; q++) {
        int i = tid + CTA * q;
        int row = i >> 4, c4 = i & 15;
        float4 zv = gz[i];
        float4 wv = *(const float4*)(W + (size_t)bidx[row] * DIM + c4 * 4);
        float zz[4] = {zv.x, zv.y, zv.z, zv.w};
        float ww[4] = {wv.x, wv.y, wv.z, wv.w};
        #pragma unroll
        for (int c = 0; c < 4; c++) {
            float dd = __fsub_rn(zz[c], ww[c]);
            lsum = __fmaf_rn(dd, dd, lsum);
            out[obase + i * 4 + c] = __fadd_rn(zz[c], __fsub_rn(ww[c], zz[c]));
        }
    }

    float* red = (float*)(sm + OFF_RED);
    red[tid] = lsum;
    __syncthreads();
    for (int s = CTA / 2; s > 0; s >>= 1) {
        if (tid < s) red[tid] = __fadd_rn(red[tid], red[tid + s]);
        __syncthreads();
    }
    __shared__ int lastf;
    if (tid == 0) {
        g_part[blockIdx.x] = red[0];
        __threadfence();
        lastf = (atomicAdd(&g_cnt, 1) == NBLK - 1) ? 1 : 0;
    }
    __syncthreads();

    if (lastf) {
        __threadfence();
        float s = __fadd_rn(g_part[tid], g_part[tid + 256]);
        red[tid] = s;
        __syncthreads();
        for (int st = CTA / 2; st > 0; st >>= 1) {
            if (tid < st) red[tid] = __fadd_rn(red[tid], red[tid + st]);
            __syncthreads();
        }
        if (tid == 0) {
            if (off) out[0] = __fmul_rn(0.25f, __fdiv_rn(red[0], 4194304.0f));
            g_cnt = 0;   // reset for next graph replay
        }
    }
}

// ---------------------------------------------------------------------------
extern "C" void kernel_launch(void* const* d_in, const int* in_sizes, int n_in,
                              void* d_out, int out_size) {
    const float* z = (const float*)d_in[0];
    const float* W = (const float*)d_in[1];
    if (n_in >= 2 && in_sizes[0] < in_sizes[1]) {
        const float* t = z; z = W; W = t;
    }
    float* out = (float*)d_out;
    const int off = (out_size > NROWS * DIM) ? 1 : 0;

    cudaFuncSetAttribute(vq_main, cudaFuncAttributeMaxDynamicSharedMemorySize,
                         SMEM_BYTES);
    prep_kernel<<<16, 256>>>(W);
    vq_main<<<NBLK, CTA, SMEM_BYTES>>>(z, W, out, off);
}